// round 16
// baseline (speedup 1.0000x reference)
#include <cuda_runtime.h>
#include <math.h>

#define BB 128
#define TT 512
#define II 256
#define HH 512
#define NTH 256
#define PK  516            // sH row pitch (floats)

typedef unsigned long long ull;

// ---------------------------------------------------------------------------
// Scratch (no cudaMalloc allowed)
// ---------------------------------------------------------------------------
__device__ float g_pre[(size_t)TT * 3 * BB * HH];   // [t][gate][b][h]
__device__ float g_h [BB * HH];
__device__ float g_z [BB * HH];
__device__ float g_rh[BB * HH];
__device__ unsigned int g_bars[8 * 32];             // fallback barrier counters
__device__ unsigned int g_done = 0;

// Packed fp32x2 FMA (SASS FFMA2) — PTX-only.
__device__ __forceinline__ void ffma2(ull& d, ull a, ull b) {
    asm("fma.rn.f32x2 %0, %1, %2, %0;" : "+l"(d) : "l"(a), "l"(b));
}
__device__ __forceinline__ float pair_sum(ull v) {
    return __uint_as_float((unsigned)v) + __uint_as_float((unsigned)(v >> 32));
}
__device__ __forceinline__ float fsig(float v) {
    return 1.0f / (1.0f + __expf(-v));
}

__device__ __forceinline__ unsigned atom_add_release(unsigned int* p, unsigned int v) {
    unsigned int old;
    asm volatile("atom.release.gpu.add.u32 %0, [%1], %2;"
                 : "=r"(old) : "l"(p), "r"(v) : "memory");
    return old;
}
__device__ __forceinline__ unsigned ld_acquire(unsigned int* p) {
    unsigned int v;
    asm volatile("ld.acquire.gpu.u32 %0, [%1];" : "=r"(v) : "l"(p) : "memory");
    return v;
}
// Fallback software group barrier (R14-proven).
__device__ __forceinline__ void group_sync_sw(unsigned int* bar, unsigned int goal) {
    __syncthreads();
    if (threadIdx.x == 0) {
        atom_add_release(bar, 1u);
        while (ld_acquire(bar) < goal) { }
    }
    __syncthreads();
}
// HW cluster barrier: arrive has .release, wait has .acquire — orders our
// global (L2) stores against peers' post-wait __ldcg loads.
__device__ __forceinline__ void cluster_sync_hw() {
    asm volatile("barrier.cluster.arrive.aligned;" ::: "memory");
    asm volatile("barrier.cluster.wait.aligned;"   ::: "memory");
}

// ---------------------------------------------------------------------------
// Precompute: pre[t][g][b][h] = dot(x[b,t,:], w_g[h,:]) + (w_bg + r_bg)
// f32x2, k-pair smem layout, 8x4 microtile, 2 CTAs/SM. (R13/R14-proven)
// ---------------------------------------------------------------------------
#define PA 260
#define PB 132

__global__ void __launch_bounds__(NTH, 2)
gru_pre_kernel(const float* __restrict__ x,
               const float* __restrict__ w_z, const float* __restrict__ w_r,
               const float* __restrict__ w_h,
               const float* __restrict__ w_bz, const float* __restrict__ w_br,
               const float* __restrict__ w_bh,
               const float* __restrict__ r_bz, const float* __restrict__ r_br,
               const float* __restrict__ r_bh)
{
    __shared__ __align__(16) float sA2[8 * PA];
    __shared__ __align__(16) float sB2[8 * PB];

    const int tid  = threadIdx.x;
    const int m0   = blockIdx.y * 128;
    const int n0   = blockIdx.x * 64;
    const int gate = n0 >> 9;
    const int hb   = n0 & (HH - 1);

    const float* W  = (gate == 0) ? w_z  : ((gate == 1) ? w_r  : w_h);
    const float* wb = (gate == 0) ? w_bz : ((gate == 1) ? w_br : w_bh);
    const float* rb = (gate == 0) ? r_bz : ((gate == 1) ? r_br : r_bh);

    const int lr  = tid & 63;
    const int lk  = (tid >> 6) << 2;
    const int k2b = lk >> 1;
    const int ty  = tid >> 4;
    const int tx  = tid & 15;

    ull acc[8][4];
#pragma unroll
    for (int i = 0; i < 8; i++)
#pragma unroll
        for (int j = 0; j < 4; j++) acc[i][j] = 0ull;

    const float* xA0 = x + (size_t)(m0 + lr)      * II + lk;
    const float* xA1 = x + (size_t)(m0 + lr + 64) * II + lk;
    const float* wB  = W + (size_t)(hb + lr)      * II + lk;

    float4 a0 = *(const float4*)(xA0);
    float4 a1 = *(const float4*)(xA1);
    float4 b0 = *(const float4*)(wB);

    for (int k0 = 0; k0 < II; k0 += 16) {
        __syncthreads();
        *(float2*)(sA2 + (k2b+0)*PA + 2*lr)        = make_float2(a0.x, a0.y);
        *(float2*)(sA2 + (k2b+1)*PA + 2*lr)        = make_float2(a0.z, a0.w);
        *(float2*)(sA2 + (k2b+0)*PA + 2*(lr + 64)) = make_float2(a1.x, a1.y);
        *(float2*)(sA2 + (k2b+1)*PA + 2*(lr + 64)) = make_float2(a1.z, a1.w);
        *(float2*)(sB2 + (k2b+0)*PB + 2*lr)        = make_float2(b0.x, b0.y);
        *(float2*)(sB2 + (k2b+1)*PB + 2*lr)        = make_float2(b0.z, b0.w);
        __syncthreads();
        if (k0 + 16 < II) {
            a0 = *(const float4*)(xA0 + k0 + 16);
            a1 = *(const float4*)(xA1 + k0 + 16);
            b0 = *(const float4*)(wB  + k0 + 16);
        }
#pragma unroll
        for (int k2 = 0; k2 < 8; k2++) {
            ulonglong2 a01 = *(const ulonglong2*)(sA2 + k2*PA + 8*ty);
            ulonglong2 a23 = *(const ulonglong2*)(sA2 + k2*PA + 8*ty + 4);
            ulonglong2 a45 = *(const ulonglong2*)(sA2 + k2*PA + 8*ty + 128);
            ulonglong2 a67 = *(const ulonglong2*)(sA2 + k2*PA + 8*ty + 132);
            ulonglong2 b01 = *(const ulonglong2*)(sB2 + k2*PB + 8*tx);
            ulonglong2 b23 = *(const ulonglong2*)(sB2 + k2*PB + 8*tx + 4);
            ull a[8] = {a01.x, a01.y, a23.x, a23.y, a45.x, a45.y, a67.x, a67.y};
            ull b[4] = {b01.x, b01.y, b23.x, b23.y};
#pragma unroll
            for (int i = 0; i < 8; i++)
#pragma unroll
                for (int j = 0; j < 4; j++)
                    ffma2(acc[i][j], a[i], b[j]);
        }
    }

    const int hcol = hb + 4*tx;
    float bias[4];
#pragma unroll
    for (int j = 0; j < 4; j++) bias[j] = wb[hcol + j] + rb[hcol + j];

#pragma unroll
    for (int i = 0; i < 8; i++) {
        int row = (i < 4) ? (4*ty + i) : (64 + 4*ty + (i - 4));
        int m = m0 + row;
        int b = m >> 9;
        int t = m & (TT - 1);
        size_t base = ((size_t)((t*3 + gate) * BB + b)) * HH + hcol;
        *(float4*)(g_pre + base) =
            make_float4(pair_sum(acc[i][0]) + bias[0], pair_sum(acc[i][1]) + bias[1],
                        pair_sum(acc[i][2]) + bias[2], pair_sum(acc[i][3]) + bias[3]);
    }
}

// ---------------------------------------------------------------------------
// Persistent scan — R16: exact R14 structure (8 groups of 16 CTAs / 16 batch
// rows, 256 threads, smem weights, same microtiles), but each group is a
// 16-CTA CGA cluster and the per-phase sync is barrier.cluster (~490 cyc)
// instead of the atomic spin barrier. use_cluster=0 falls back to R14 path.
// ---------------------------------------------------------------------------
#define SW1_F (256 * 128)
#define SW2_F (256 * 64)
#define SMEM_SH (SW1_F + SW2_F)
#define SCAN_SMEM_BYTES ((SW1_F + SW2_F + 16 * PK) * 4)   // 229,632 B

__device__ __forceinline__ void stage16x512(const float* __restrict__ src,
                                            float* sH, int b0t, int tid) {
#pragma unroll
    for (int i = 0; i < 8; i++) {
        int idx = i * NTH + tid;
        int row = idx >> 7, k4 = idx & 127;
        float4 v = __ldcg((const float4*)(src + (size_t)(b0t + row) * HH + 4 * k4));
        *(float4*)(sH + row * PK + 4 * k4) = v;
    }
}

__global__ void __launch_bounds__(NTH, 1)
gru_scan_kernel(const float* __restrict__ h0,
                const float* __restrict__ r_z, const float* __restrict__ r_r,
                const float* __restrict__ r_h,
                float* __restrict__ out, int write_hlast, int use_cluster)
{
    extern __shared__ __align__(16) float sm[];
    float* sW1 = sm;                 // [k2][2*j], j 0..63
    float* sW2 = sm + SW1_F;         // [k2][2*j], j 0..31
    float* sH  = sm + SMEM_SH;       // [row][PK], 16 rows

    const int tid  = threadIdx.x;
    const int bid  = blockIdx.x;
    const int lane = tid & 31;
    const int w    = tid >> 5;
    const int mt   = bid >> 4;           // group == cluster
    const int nt   = bid & 15;
    const int b0t   = mt * 16;
    const int p2_j0 = nt * 32;
    const int gate  = (nt < 8) ? 0 : 1;
    const int jj0   = (nt & 7) * 64;

    unsigned int* bar = &g_bars[mt * 32];
    const float* Rzr = gate ? r_r : r_z;

    // ---- persistent weight tiles -> smem ----
#pragma unroll
    for (int i = 0; i < 32; i++) {
        int idx = i * NTH + tid;
        int j = idx >> 7, k4 = idx & 127;
        float4 v = *(const float4*)(Rzr + (size_t)(jj0 + j) * HH + 4 * k4);
        *(float2*)(sW1 + (2*k4)   * 128 + 2*j) = make_float2(v.x, v.y);
        *(float2*)(sW1 + (2*k4+1) * 128 + 2*j) = make_float2(v.z, v.w);
    }
#pragma unroll
    for (int i = 0; i < 16; i++) {
        int idx = i * NTH + tid;
        int j = idx >> 7, k4 = idx & 127;
        float4 v = *(const float4*)(r_h + (size_t)(p2_j0 + j) * HH + 4 * k4);
        *(float2*)(sW2 + (2*k4)   * 64 + 2*j) = make_float2(v.x, v.y);
        *(float2*)(sW2 + (2*k4+1) * 64 + 2*j) = make_float2(v.z, v.w);
    }

    // ph1 mapping: warp = 8r x 16c, lane = 2r x 2c
    const int q1  = lane >> 3;
    const int cp1 = lane & 7;
    const int r1a = 8 * (w & 1) + 2 * q1;
    const int c1  = 16 * (w >> 1) + 2 * cp1;
    // ph2 mapping: warp = 4r x 16c, lane = 2r x 1c
    const int q2  = lane >> 4;
    const int c2  = lane & 15;
    const int r2a = 4 * (w & 3) + 2 * q2;
    const int c2f = 16 * (w >> 2) + c2;

    // ---- init h state ----
    {
        int base = bid * 512 + tid * 2;        // CTA bid owns g_h row bid
        g_h[base]     = h0[base];
        g_h[base + 1] = h0[base + 1];
    }
    const int grow2 = b0t + r2a;
    const int gj2   = p2_j0 + c2f;
    float hreg0 = h0[(size_t)grow2       * HH + gj2];
    float hreg1 = h0[(size_t)(grow2 + 1) * HH + gj2];

    unsigned int nbar = 0;
    if (use_cluster) cluster_sync_hw();
    else             group_sync_sw(bar, ++nbar * 16);

    const float* hp1a = sH + r1a * PK;
    const float* hp1b = hp1a + PK;
    const float* wp1  = sW1 + 2 * c1;
    const float* hp2a = sH + r2a * PK;
    const float* hp2b = hp2a + PK;
    const float* wp2  = sW2 + 2 * c2f;

    const int row1 = b0t + r1a;
    const int col1 = jj0 + c1;

    for (int t = 0; t < TT; t++) {
        // ================= phase 1: z / r gates =================
        const float* pre1 = g_pre + (size_t)(t*3 + gate) * BB * HH;
        float2 pv0 = __ldcg((const float2*)(pre1 + (size_t)row1       * HH + col1));
        float2 pv1 = __ldcg((const float2*)(pre1 + (size_t)(row1 + 1) * HH + col1));

        stage16x512(g_h, sH, b0t, tid);
        __syncthreads();
        {
            ull a00 = 0ull, a01 = 0ull, a10 = 0ull, a11 = 0ull;
#pragma unroll 4
            for (int k4 = 0; k4 < 128; k4++) {
                ulonglong2 hv0 = *(const ulonglong2*)(hp1a + 4 * k4);
                ulonglong2 hv1 = *(const ulonglong2*)(hp1b + 4 * k4);
                ulonglong2 w0  = *(const ulonglong2*)(wp1 + (2*k4)   * 128);
                ulonglong2 w1  = *(const ulonglong2*)(wp1 + (2*k4+1) * 128);
                ffma2(a00, hv0.x, w0.x); ffma2(a01, hv0.x, w0.y);
                ffma2(a10, hv1.x, w0.x); ffma2(a11, hv1.x, w0.y);
                ffma2(a00, hv0.y, w1.x); ffma2(a01, hv0.y, w1.y);
                ffma2(a10, hv1.y, w1.x); ffma2(a11, hv1.y, w1.y);
            }
            float v00 = fsig(pair_sum(a00) + pv0.x);
            float v01 = fsig(pair_sum(a01) + pv0.y);
            float v10 = fsig(pair_sum(a10) + pv1.x);
            float v11 = fsig(pair_sum(a11) + pv1.y);
            if (gate == 0) {
                *(float2*)(g_z + (size_t)row1       * HH + col1) = make_float2(v00, v01);
                *(float2*)(g_z + (size_t)(row1 + 1) * HH + col1) = make_float2(v10, v11);
            } else {
                float2 h0v = *(const float2*)(hp1a + col1);
                float2 h1v = *(const float2*)(hp1b + col1);
                *(float2*)(g_rh + (size_t)row1       * HH + col1) =
                    make_float2(v00 * h0v.x, v01 * h0v.y);
                *(float2*)(g_rh + (size_t)(row1 + 1) * HH + col1) =
                    make_float2(v10 * h1v.x, v11 * h1v.y);
            }
        }
        if (use_cluster) cluster_sync_hw();
        else             group_sync_sw(bar, ++nbar * 16);

        // ================= phase 2: candidate + update =================
        const float* pre2 = g_pre + (size_t)(t*3 + 2) * BB * HH;
        float pz0 = __ldcg(pre2 + (size_t)grow2       * HH + gj2);
        float pz1 = __ldcg(pre2 + (size_t)(grow2 + 1) * HH + gj2);
        float z0  = __ldcg(g_z + (size_t)grow2       * HH + gj2);
        float z1  = __ldcg(g_z + (size_t)(grow2 + 1) * HH + gj2);

        stage16x512(g_rh, sH, b0t, tid);
        __syncthreads();
        {
            ull acc0 = 0ull, acc1 = 0ull;
#pragma unroll 4
            for (int k4 = 0; k4 < 128; k4++) {
                ulonglong2 hv0 = *(const ulonglong2*)(hp2a + 4 * k4);
                ulonglong2 hv1 = *(const ulonglong2*)(hp2b + 4 * k4);
                ull w0 = *(const ull*)(wp2 + (2*k4)   * 64);
                ull w1 = *(const ull*)(wp2 + (2*k4+1) * 64);
                ffma2(acc0, hv0.x, w0); ffma2(acc0, hv0.y, w1);
                ffma2(acc1, hv1.x, w0); ffma2(acc1, hv1.y, w1);
            }
            float hh0 = tanhf(pair_sum(acc0) + pz0);
            float hh1 = tanhf(pair_sum(acc1) + pz1);
            float hn0 = (1.0f - z0) * hh0 + z0 * hreg0;
            float hn1 = (1.0f - z1) * hh1 + z1 * hreg1;
            hreg0 = hn0; hreg1 = hn1;
            g_h[(size_t)grow2       * HH + gj2] = hn0;
            g_h[(size_t)(grow2 + 1) * HH + gj2] = hn1;
            out[((size_t)grow2       * TT + t) * HH + gj2] = hn0;
            out[((size_t)(grow2 + 1) * TT + t) * HH + gj2] = hn1;
            if (write_hlast && t == TT - 1) {
                out[(size_t)BB*TT*HH + (size_t)grow2       * HH + gj2] = hn0;
                out[(size_t)BB*TT*HH + (size_t)(grow2 + 1) * HH + gj2] = hn1;
            }
        }
        if (use_cluster) cluster_sync_hw();
        else             group_sync_sw(bar, ++nbar * 16);
    }

    // Fallback-only: reset software barrier state for the next graph replay.
    if (!use_cluster) {
        __syncthreads();
        if (tid == 0) {
            unsigned int old = atom_add_release(&g_done, 1u);
            if (old == BB - 1) {
#pragma unroll
                for (int g = 0; g < 8; g++) g_bars[g * 32] = 0;
                g_done = 0;
                __threadfence();
            }
        }
    }
}

// ---------------------------------------------------------------------------
extern "C" void kernel_launch(void* const* d_in, const int* in_sizes, int n_in,
                              void* d_out, int out_size)
{
    const float* x    = (const float*)d_in[0];
    const float* h0   = (const float*)d_in[1];
    const float* w_z  = (const float*)d_in[2];
    const float* w_r  = (const float*)d_in[3];
    const float* w_h  = (const float*)d_in[4];
    const float* r_z  = (const float*)d_in[5];
    const float* r_r  = (const float*)d_in[6];
    const float* r_h  = (const float*)d_in[7];
    const float* w_bz = (const float*)d_in[8];
    const float* w_br = (const float*)d_in[9];
    const float* w_bh = (const float*)d_in[10];
    const float* r_bz = (const float*)d_in[11];
    const float* r_br = (const float*)d_in[12];
    const float* r_bh = (const float*)d_in[13];
    float* out = (float*)d_out;

    (void)in_sizes; (void)n_in;

    cudaFuncSetAttribute(gru_scan_kernel,
                         cudaFuncAttributeMaxDynamicSharedMemorySize,
                         SCAN_SMEM_BYTES);

    dim3 gpre(1536 / 64, (BB * TT) / 128);
    gru_pre_kernel<<<gpre, NTH>>>(x, w_z, w_r, w_h,
                                  w_bz, w_br, w_bh, r_bz, r_br, r_bh);

    int write_hlast = (out_size >= (int)(BB * TT * HH + BB * HH)) ? 1 : 0;

    // Prefer 16-CTA clusters (nonportable size); deterministic fallback to the
    // R14 software-barrier path if the attribute or launch is rejected.
    cudaError_t rc = cudaFuncSetAttribute(
        gru_scan_kernel, cudaFuncAttributeNonPortableClusterSizeAllowed, 1);
    bool launched = false;
    if (rc == cudaSuccess) {
        cudaLaunchConfig_t cfg = {};
        cfg.gridDim  = dim3(BB, 1, 1);
        cfg.blockDim = dim3(NTH, 1, 1);
        cfg.dynamicSmemBytes = SCAN_SMEM_BYTES;
        cfg.stream = 0;
        cudaLaunchAttribute attrs[1];
        attrs[0].id = cudaLaunchAttributeClusterDimension;
        attrs[0].val.clusterDim.x = 16;
        attrs[0].val.clusterDim.y = 1;
        attrs[0].val.clusterDim.z = 1;
        cfg.attrs = attrs;
        cfg.numAttrs = 1;
        cudaError_t e = cudaLaunchKernelEx(&cfg, gru_scan_kernel,
                                           h0, r_z, r_r, r_h, out,
                                           write_hlast, 1);
        launched = (e == cudaSuccess);
        if (!launched) (void)cudaGetLastError();   // clear sticky error
    } else {
        (void)cudaGetLastError();
    }
    if (!launched) {
        gru_scan_kernel<<<BB, NTH, SCAN_SMEM_BYTES>>>(h0, r_z, r_r, r_h, out,
                                                      write_hlast, 0);
    }
}

// round 17
// speedup vs baseline: 1.9669x; 1.9669x over previous
#include <cuda_runtime.h>
#include <math.h>

#define BB 128
#define TT 512
#define II 256
#define HH 512
#define NTH 256

typedef unsigned long long ull;

// ---------------------------------------------------------------------------
// Scratch (no cudaMalloc allowed)
// ---------------------------------------------------------------------------
__device__ float g_pre[(size_t)TT * 3 * BB * HH];   // [t][gate][b][h]
__device__ float g_h [BB * HH];
__device__ float g_z [BB * HH];
__device__ float g_rh[BB * HH];
__device__ unsigned int g_bars[8 * 32];             // 8 group counters, 128B apart
__device__ unsigned int g_done = 0;

// Packed fp32x2 FMA (SASS FFMA2) — PTX-only.
__device__ __forceinline__ void ffma2(ull& d, ull a, ull b) {
    asm("fma.rn.f32x2 %0, %1, %2, %0;" : "+l"(d) : "l"(a), "l"(b));
}
__device__ __forceinline__ float pair_sum(ull v) {
    return __uint_as_float((unsigned)v) + __uint_as_float((unsigned)(v >> 32));
}
__device__ __forceinline__ float fsig(float v) {
    return 1.0f / (1.0f + __expf(-v));
}

__device__ __forceinline__ unsigned atom_add_release(unsigned int* p, unsigned int v) {
    unsigned int old;
    asm volatile("atom.release.gpu.add.u32 %0, [%1], %2;"
                 : "=r"(old) : "l"(p), "r"(v) : "memory");
    return old;
}
__device__ __forceinline__ unsigned ld_acquire(unsigned int* p) {
    unsigned int v;
    asm volatile("ld.acquire.gpu.u32 %0, [%1];" : "=r"(v) : "l"(p) : "memory");
    return v;
}
__device__ __forceinline__ void group_sync(unsigned int* bar, unsigned int goal) {
    __syncthreads();
    if (threadIdx.x == 0) {
        atom_add_release(bar, 1u);
        while (ld_acquire(bar) < goal) { }
    }
    __syncthreads();
}

// ---------------------------------------------------------------------------
// Precompute: pre[t][g][b][h] = dot(x[b,t,:], w_g[h,:]) + (w_bg + r_bg)
// (R13/R14-proven, unchanged)
// ---------------------------------------------------------------------------
#define PA 260
#define PB 132

__global__ void __launch_bounds__(NTH, 2)
gru_pre_kernel(const float* __restrict__ x,
               const float* __restrict__ w_z, const float* __restrict__ w_r,
               const float* __restrict__ w_h,
               const float* __restrict__ w_bz, const float* __restrict__ w_br,
               const float* __restrict__ w_bh,
               const float* __restrict__ r_bz, const float* __restrict__ r_br,
               const float* __restrict__ r_bh)
{
    __shared__ __align__(16) float sA2[8 * PA];
    __shared__ __align__(16) float sB2[8 * PB];

    const int tid  = threadIdx.x;
    const int m0   = blockIdx.y * 128;
    const int n0   = blockIdx.x * 64;
    const int gate = n0 >> 9;
    const int hb   = n0 & (HH - 1);

    const float* W  = (gate == 0) ? w_z  : ((gate == 1) ? w_r  : w_h);
    const float* wb = (gate == 0) ? w_bz : ((gate == 1) ? w_br : w_bh);
    const float* rb = (gate == 0) ? r_bz : ((gate == 1) ? r_br : r_bh);

    const int lr  = tid & 63;
    const int lk  = (tid >> 6) << 2;
    const int k2b = lk >> 1;
    const int ty  = tid >> 4;
    const int tx  = tid & 15;

    ull acc[8][4];
#pragma unroll
    for (int i = 0; i < 8; i++)
#pragma unroll
        for (int j = 0; j < 4; j++) acc[i][j] = 0ull;

    const float* xA0 = x + (size_t)(m0 + lr)      * II + lk;
    const float* xA1 = x + (size_t)(m0 + lr + 64) * II + lk;
    const float* wB  = W + (size_t)(hb + lr)      * II + lk;

    float4 a0 = *(const float4*)(xA0);
    float4 a1 = *(const float4*)(xA1);
    float4 b0 = *(const float4*)(wB);

    for (int k0 = 0; k0 < II; k0 += 16) {
        __syncthreads();
        *(float2*)(sA2 + (k2b+0)*PA + 2*lr)        = make_float2(a0.x, a0.y);
        *(float2*)(sA2 + (k2b+1)*PA + 2*lr)        = make_float2(a0.z, a0.w);
        *(float2*)(sA2 + (k2b+0)*PA + 2*(lr + 64)) = make_float2(a1.x, a1.y);
        *(float2*)(sA2 + (k2b+1)*PA + 2*(lr + 64)) = make_float2(a1.z, a1.w);
        *(float2*)(sB2 + (k2b+0)*PB + 2*lr)        = make_float2(b0.x, b0.y);
        *(float2*)(sB2 + (k2b+1)*PB + 2*lr)        = make_float2(b0.z, b0.w);
        __syncthreads();
        if (k0 + 16 < II) {
            a0 = *(const float4*)(xA0 + k0 + 16);
            a1 = *(const float4*)(xA1 + k0 + 16);
            b0 = *(const float4*)(wB  + k0 + 16);
        }
#pragma unroll
        for (int k2 = 0; k2 < 8; k2++) {
            ulonglong2 a01 = *(const ulonglong2*)(sA2 + k2*PA + 8*ty);
            ulonglong2 a23 = *(const ulonglong2*)(sA2 + k2*PA + 8*ty + 4);
            ulonglong2 a45 = *(const ulonglong2*)(sA2 + k2*PA + 8*ty + 128);
            ulonglong2 a67 = *(const ulonglong2*)(sA2 + k2*PA + 8*ty + 132);
            ulonglong2 b01 = *(const ulonglong2*)(sB2 + k2*PB + 8*tx);
            ulonglong2 b23 = *(const ulonglong2*)(sB2 + k2*PB + 8*tx + 4);
            ull a[8] = {a01.x, a01.y, a23.x, a23.y, a45.x, a45.y, a67.x, a67.y};
            ull b[4] = {b01.x, b01.y, b23.x, b23.y};
#pragma unroll
            for (int i = 0; i < 8; i++)
#pragma unroll
                for (int j = 0; j < 4; j++)
                    ffma2(acc[i][j], a[i], b[j]);
        }
    }

    const int hcol = hb + 4*tx;
    float bias[4];
#pragma unroll
    for (int j = 0; j < 4; j++) bias[j] = wb[hcol + j] + rb[hcol + j];

#pragma unroll
    for (int i = 0; i < 8; i++) {
        int row = (i < 4) ? (4*ty + i) : (64 + 4*ty + (i - 4));
        int m = m0 + row;
        int b = m >> 9;
        int t = m & (TT - 1);
        size_t base = ((size_t)((t*3 + gate) * BB + b)) * HH + hcol;
        *(float4*)(g_pre + base) =
            make_float4(pair_sum(acc[i][0]) + bias[0], pair_sum(acc[i][1]) + bias[1],
                        pair_sum(acc[i][2]) + bias[2], pair_sum(acc[i][3]) + bias[3]);
    }
}

// ---------------------------------------------------------------------------
// Persistent scan — R17: R14 group structure (8 groups x 16 CTAs / 16 rows,
// software barriers), GEMM micro-structure redesigned to cut LDS bytes/MAC:
//   thread tile 4r x 4c, K split across warps, smem partial reduction.
//   ph1 (16x64, K=512): warp (Q=w&3 k-quarter, Chalf=w>>2); lane (R=lane>>3,
//       c8=lane&7). Per k4/thread: 4 LDS.128 h (XOR-swizzled, conflict-free)
//       + 4 LDS.128 w for 32 FFMA2  (~1 B/MAC effective at warp level).
//   ph2 (16x32, K=512): warp = k-eighth Q2=w; same lane tile.
//   Partials (16KB) overlay sH (dead after GEMM); cheap reduce + epilogue.
// smem: sW1 128KB | sW2 64KB | sH 32KB (pitch 512, k4^=(row>>2)&3 swizzle).
// ---------------------------------------------------------------------------
#define SW1_F (256 * 128)                 // floats
#define SW2_F (256 * 64)
#define SH_OFF (SW1_F + SW2_F)
#define SCAN_SMEM_BYTES ((SW1_F + SW2_F + 16 * 512) * 4)   // 229,376 B

__device__ __forceinline__ void stage16x512(const float* __restrict__ src,
                                            float* sH, int b0t, int tid) {
#pragma unroll
    for (int i = 0; i < 8; i++) {
        int idx = i * NTH + tid;            // 0..2047
        int row = idx >> 7, k4 = idx & 127;
        float4 v = __ldcg((const float4*)(src + (size_t)(b0t + row) * HH + 4 * k4));
        *(float4*)(sH + row * 512 + ((k4 ^ ((row >> 2) & 3)) << 2)) = v;
    }
}

__global__ void __launch_bounds__(NTH, 1)
gru_scan_kernel(const float* __restrict__ h0,
                const float* __restrict__ r_z, const float* __restrict__ r_r,
                const float* __restrict__ r_h,
                float* __restrict__ out, int write_hlast)
{
    extern __shared__ __align__(16) float sm[];
    float* sW1   = sm;                // [k2][2*j], j 0..63
    float* sW2   = sm + SW1_F;        // [k2][2*j], j 0..31
    float* sH    = sm + SH_OFF;       // [16][512] swizzled
    float* sPart = sH;                // overlay: partials live while sH is dead

    const int tid  = threadIdx.x;
    const int bid  = blockIdx.x;
    const int lane = tid & 31;
    const int w    = tid >> 5;
    const int mt   = bid >> 4;            // group 0..7
    const int nt   = bid & 15;
    const int b0t   = mt * 16;
    const int p2_j0 = nt * 32;
    const int gate  = (nt < 8) ? 0 : 1;
    const int jj0   = (nt & 7) * 64;

    unsigned int* bar = &g_bars[mt * 32];
    const float* Rzr = gate ? r_r : r_z;

    // ---- persistent weight tiles -> smem (k-pair interleaved) ----
#pragma unroll
    for (int i = 0; i < 32; i++) {
        int idx = i * NTH + tid;            // 0..8191
        int j = idx >> 7, k4 = idx & 127;   // j 0..63
        float4 v = *(const float4*)(Rzr + (size_t)(jj0 + j) * HH + 4 * k4);
        *(float2*)(sW1 + (2*k4)   * 128 + 2*j) = make_float2(v.x, v.y);
        *(float2*)(sW1 + (2*k4+1) * 128 + 2*j) = make_float2(v.z, v.w);
    }
#pragma unroll
    for (int i = 0; i < 16; i++) {
        int idx = i * NTH + tid;            // 0..4095
        int j = idx >> 7, k4 = idx & 127;   // j 0..31
        float4 v = *(const float4*)(r_h + (size_t)(p2_j0 + j) * HH + 4 * k4);
        *(float2*)(sW2 + (2*k4)   * 64 + 2*j) = make_float2(v.x, v.y);
        *(float2*)(sW2 + (2*k4+1) * 64 + 2*j) = make_float2(v.z, v.w);
    }

    // ---- GEMM lane mapping (shared by both phases) ----
    const int R  = lane >> 3;               // row-group: rows 4R..4R+3
    const int C1 = 8 * (w >> 2) + (lane & 7);  // ph1 col-group 0..15 (cols 4C1..)
    const int Q1 = w & 3;                      // ph1 k-quarter
    const int C2 = lane & 7;                   // ph2 col-group 0..7
    const int Q2 = w;                          // ph2 k-eighth

    // ---- reduction/epilogue output mapping ----
    const int rt1 = tid >> 4;               // 0..15
    const int ct1 = 4 * (tid & 15);         // 0..60
    const int row1 = b0t + rt1;
    const int col1 = jj0 + ct1;             // H-space col (ph1, this gate)
    const int rt2 = tid >> 4;
    const int ct2 = 2 * (tid & 15);
    const int grow2 = b0t + rt2;
    const int gj2   = p2_j0 + ct2;

    // ---- init h state ----
    {
        int base = bid * 512 + tid * 2;     // CTA bid owns g_h row bid
        g_h[base]     = h0[base];
        g_h[base + 1] = h0[base + 1];
    }
    float2 hreg = *(const float2*)(h0 + (size_t)grow2 * HH + gj2);

    unsigned int nbar = 0;
    group_sync(bar, ++nbar * 16);

    for (int t = 0; t < TT; t++) {
        // ================= phase 1: z / r gates =================
        const float* pre1 = g_pre + (size_t)(t*3 + gate) * BB * HH;
        float4 pv = __ldcg((const float4*)(pre1 + (size_t)row1 * HH + col1));
        float4 hv4 = __ldcg((const float4*)(g_h + (size_t)row1 * HH + col1));

        stage16x512(g_h, sH, b0t, tid);
        __syncthreads();
        {
            ull acc[4][4];
#pragma unroll
            for (int r = 0; r < 4; r++)
#pragma unroll
                for (int c = 0; c < 4; c++) acc[r][c] = 0ull;

            const float* h0p = sH + (4*R + 0) * 512;
            const float* h1p = sH + (4*R + 1) * 512;
            const float* h2p = sH + (4*R + 2) * 512;
            const float* h3p = sH + (4*R + 3) * 512;

#pragma unroll 2
            for (int k4 = Q1*32; k4 < Q1*32 + 32; k4++) {
                const int kx = (k4 ^ R) << 2;
                ulonglong2 hv0 = *(const ulonglong2*)(h0p + kx);
                ulonglong2 hv1 = *(const ulonglong2*)(h1p + kx);
                ulonglong2 hv2 = *(const ulonglong2*)(h2p + kx);
                ulonglong2 hv3 = *(const ulonglong2*)(h3p + kx);
                const float* wba = sW1 + (2*k4) * 128 + 8*C1;
                ulonglong2 wa01 = *(const ulonglong2*)(wba);
                ulonglong2 wa23 = *(const ulonglong2*)(wba + 4);
                ulonglong2 wb01 = *(const ulonglong2*)(wba + 128);
                ulonglong2 wb23 = *(const ulonglong2*)(wba + 132);
                ffma2(acc[0][0], hv0.x, wa01.x); ffma2(acc[0][1], hv0.x, wa01.y);
                ffma2(acc[0][2], hv0.x, wa23.x); ffma2(acc[0][3], hv0.x, wa23.y);
                ffma2(acc[1][0], hv1.x, wa01.x); ffma2(acc[1][1], hv1.x, wa01.y);
                ffma2(acc[1][2], hv1.x, wa23.x); ffma2(acc[1][3], hv1.x, wa23.y);
                ffma2(acc[2][0], hv2.x, wa01.x); ffma2(acc[2][1], hv2.x, wa01.y);
                ffma2(acc[2][2], hv2.x, wa23.x); ffma2(acc[2][3], hv2.x, wa23.y);
                ffma2(acc[3][0], hv3.x, wa01.x); ffma2(acc[3][1], hv3.x, wa01.y);
                ffma2(acc[3][2], hv3.x, wa23.x); ffma2(acc[3][3], hv3.x, wa23.y);
                ffma2(acc[0][0], hv0.y, wb01.x); ffma2(acc[0][1], hv0.y, wb01.y);
                ffma2(acc[0][2], hv0.y, wb23.x); ffma2(acc[0][3], hv0.y, wb23.y);
                ffma2(acc[1][0], hv1.y, wb01.x); ffma2(acc[1][1], hv1.y, wb01.y);
                ffma2(acc[1][2], hv1.y, wb23.x); ffma2(acc[1][3], hv1.y, wb23.y);
                ffma2(acc[2][0], hv2.y, wb01.x); ffma2(acc[2][1], hv2.y, wb01.y);
                ffma2(acc[2][2], hv2.y, wb23.x); ffma2(acc[2][3], hv2.y, wb23.y);
                ffma2(acc[3][0], hv3.y, wb01.x); ffma2(acc[3][1], hv3.y, wb01.y);
                ffma2(acc[3][2], hv3.y, wb23.x); ffma2(acc[3][3], hv3.y, wb23.y);
            }
            __syncthreads();   // sH(h) dead; safe to overlay partials
#pragma unroll
            for (int r = 0; r < 4; r++)
                *(float4*)(sPart + Q1*1024 + (4*R + r)*64 + 4*C1) =
                    make_float4(pair_sum(acc[r][0]), pair_sum(acc[r][1]),
                                pair_sum(acc[r][2]), pair_sum(acc[r][3]));
            __syncthreads();
        }
        {   // reduce 4 k-quarters + epilogue
            float4 s = make_float4(0.f, 0.f, 0.f, 0.f);
#pragma unroll
            for (int q = 0; q < 4; q++) {
                float4 v = *(const float4*)(sPart + q*1024 + rt1*64 + ct1);
                s.x += v.x; s.y += v.y; s.z += v.z; s.w += v.w;
            }
            float v0 = fsig(s.x + pv.x), v1 = fsig(s.y + pv.y);
            float v2 = fsig(s.z + pv.z), v3 = fsig(s.w + pv.w);
            if (gate == 0) {
                *(float4*)(g_z + (size_t)row1 * HH + col1) =
                    make_float4(v0, v1, v2, v3);
            } else {
                *(float4*)(g_rh + (size_t)row1 * HH + col1) =
                    make_float4(v0 * hv4.x, v1 * hv4.y, v2 * hv4.z, v3 * hv4.w);
            }
        }
        group_sync(bar, ++nbar * 16);

        // ================= phase 2: candidate + update =================
        const float* pre2 = g_pre + (size_t)(t*3 + 2) * BB * HH;
        float2 pz = __ldcg((const float2*)(pre2 + (size_t)grow2 * HH + gj2));
        float2 zv = __ldcg((const float2*)(g_z + (size_t)grow2 * HH + gj2));

        stage16x512(g_rh, sH, b0t, tid);
        __syncthreads();
        {
            ull acc[4][4];
#pragma unroll
            for (int r = 0; r < 4; r++)
#pragma unroll
                for (int c = 0; c < 4; c++) acc[r][c] = 0ull;

            const float* h0p = sH + (4*R + 0) * 512;
            const float* h1p = sH + (4*R + 1) * 512;
            const float* h2p = sH + (4*R + 2) * 512;
            const float* h3p = sH + (4*R + 3) * 512;

#pragma unroll 2
            for (int k4 = Q2*16; k4 < Q2*16 + 16; k4++) {
                const int kx = (k4 ^ R) << 2;
                ulonglong2 hv0 = *(const ulonglong2*)(h0p + kx);
                ulonglong2 hv1 = *(const ulonglong2*)(h1p + kx);
                ulonglong2 hv2 = *(const ulonglong2*)(h2p + kx);
                ulonglong2 hv3 = *(const ulonglong2*)(h3p + kx);
                const float* wba = sW2 + (2*k4) * 64 + 8*C2;
                ulonglong2 wa01 = *(const ulonglong2*)(wba);
                ulonglong2 wa23 = *(const ulonglong2*)(wba + 4);
                ulonglong2 wb01 = *(const ulonglong2*)(wba + 64);
                ulonglong2 wb23 = *(const ulonglong2*)(wba + 68);
                ffma2(acc[0][0], hv0.x, wa01.x); ffma2(acc[0][1], hv0.x, wa01.y);
                ffma2(acc[0][2], hv0.x, wa23.x); ffma2(acc[0][3], hv0.x, wa23.y);
                ffma2(acc[1][0], hv1.x, wa01.x); ffma2(acc[1][1], hv1.x, wa01.y);
                ffma2(acc[1][2], hv1.x, wa23.x); ffma2(acc[1][3], hv1.x, wa23.y);
                ffma2(acc[2][0], hv2.x, wa01.x); ffma2(acc[2][1], hv2.x, wa01.y);
                ffma2(acc[2][2], hv2.x, wa23.x); ffma2(acc[2][3], hv2.x, wa23.y);
                ffma2(acc[3][0], hv3.x, wa01.x); ffma2(acc[3][1], hv3.x, wa01.y);
                ffma2(acc[3][2], hv3.x, wa23.x); ffma2(acc[3][3], hv3.x, wa23.y);
                ffma2(acc[0][0], hv0.y, wb01.x); ffma2(acc[0][1], hv0.y, wb01.y);
                ffma2(acc[0][2], hv0.y, wb23.x); ffma2(acc[0][3], hv0.y, wb23.y);
                ffma2(acc[1][0], hv1.y, wb01.x); ffma2(acc[1][1], hv1.y, wb01.y);
                ffma2(acc[1][2], hv1.y, wb23.x); ffma2(acc[1][3], hv1.y, wb23.y);
                ffma2(acc[2][0], hv2.y, wb01.x); ffma2(acc[2][1], hv2.y, wb01.y);
                ffma2(acc[2][2], hv2.y, wb23.x); ffma2(acc[2][3], hv2.y, wb23.y);
                ffma2(acc[3][0], hv3.y, wb01.x); ffma2(acc[3][1], hv3.y, wb01.y);
                ffma2(acc[3][2], hv3.y, wb23.x); ffma2(acc[3][3], hv3.y, wb23.y);
            }
            __syncthreads();   // sH(rh) dead; overlay partials
#pragma unroll
            for (int r = 0; r < 4; r++)
                *(float4*)(sPart + Q2*512 + (4*R + r)*32 + 4*C2) =
                    make_float4(pair_sum(acc[r][0]), pair_sum(acc[r][1]),
                                pair_sum(acc[r][2]), pair_sum(acc[r][3]));
            __syncthreads();
        }
        {   // reduce 8 k-eighths + fused update
            float s0 = 0.f, s1 = 0.f;
#pragma unroll
            for (int q = 0; q < 8; q++) {
                float2 v = *(const float2*)(sPart + q*512 + rt2*32 + ct2);
                s0 += v.x; s1 += v.y;
            }
            float hh0 = tanhf(s0 + pz.x);
            float hh1 = tanhf(s1 + pz.y);
            float hn0 = (1.0f - zv.x) * hh0 + zv.x * hreg.x;
            float hn1 = (1.0f - zv.y) * hh1 + zv.y * hreg.y;
            hreg.x = hn0; hreg.y = hn1;
            *(float2*)(g_h + (size_t)grow2 * HH + gj2) = make_float2(hn0, hn1);
            *(float2*)(out + ((size_t)grow2 * TT + t) * HH + gj2) = make_float2(hn0, hn1);
            if (write_hlast && t == TT - 1)
                *(float2*)(out + (size_t)BB*TT*HH + (size_t)grow2 * HH + gj2) =
                    make_float2(hn0, hn1);
        }
        group_sync(bar, ++nbar * 16);
    }

    // Reset barrier state for the next graph replay (last CTA overall).
    __syncthreads();
    if (tid == 0) {
        unsigned int old = atom_add_release(&g_done, 1u);
        if (old == BB - 1) {
#pragma unroll
            for (int g = 0; g < 8; g++) g_bars[g * 32] = 0;
            g_done = 0;
            __threadfence();
        }
    }
}

// ---------------------------------------------------------------------------
extern "C" void kernel_launch(void* const* d_in, const int* in_sizes, int n_in,
                              void* d_out, int out_size)
{
    const float* x    = (const float*)d_in[0];
    const float* h0   = (const float*)d_in[1];
    const float* w_z  = (const float*)d_in[2];
    const float* w_r  = (const float*)d_in[3];
    const float* w_h  = (const float*)d_in[4];
    const float* r_z  = (const float*)d_in[5];
    const float* r_r  = (const float*)d_in[6];
    const float* r_h  = (const float*)d_in[7];
    const float* w_bz = (const float*)d_in[8];
    const float* w_br = (const float*)d_in[9];
    const float* w_bh = (const float*)d_in[10];
    const float* r_bz = (const float*)d_in[11];
    const float* r_br = (const float*)d_in[12];
    const float* r_bh = (const float*)d_in[13];
    float* out = (float*)d_out;

    (void)in_sizes; (void)n_in;

    cudaFuncSetAttribute(gru_scan_kernel,
                         cudaFuncAttributeMaxDynamicSharedMemorySize,
                         SCAN_SMEM_BYTES);

    dim3 gpre(1536 / 64, (BB * TT) / 128);
    gru_pre_kernel<<<gpre, NTH>>>(x, w_z, w_r, w_h,
                                  w_bz, w_br, w_bh, r_bz, r_br, r_bh);

    int write_hlast = (out_size >= (int)(BB * TT * HH + BB * HH)) ? 1 : 0;
    gru_scan_kernel<<<BB, NTH, SCAN_SMEM_BYTES>>>(h0, r_z, r_r, r_h, out, write_hlast);
}